// round 1
// baseline (speedup 1.0000x reference)
#include <cuda_runtime.h>
#include <cstdint>

#define B_DIM 1024
#define L_DIM 50
#define P_DIM 10
#define D_DIM 64
#define V_DIM 100000

#define BM 128
#define BN 128
#define KS 68  // padded smem stride (floats): 68 % 32 == 4 -> conflict-free frags

// Scratch for the prep result x[B, D] (device global: no allocs allowed)
__device__ float g_x[B_DIM * D_DIM];

__device__ __forceinline__ uint32_t cvt_tf32(float f) {
    uint32_t r;
    asm("cvt.rna.tf32.f32 %0, %1;" : "=r"(r) : "f"(f));
    return r;
}

// ---------------------------------------------------------------------------
// Kernel 1: x[b,d] = user_emb[uid[b],d] + low + high + high^2*(S + S^2 + S^3)
// ---------------------------------------------------------------------------
__global__ void prep_kernel(const int* __restrict__ item_seq,
                            const int* __restrict__ user_ids,
                            const float* __restrict__ item_emb,
                            const float* __restrict__ user_emb) {
    __shared__ int sidx[L_DIM];
    int b = blockIdx.x;
    int d = threadIdx.x;
    if (d < L_DIM) sidx[d] = item_seq[b * L_DIM + d];
    __syncthreads();

    float S = 0.f, Slast = 0.f;
#pragma unroll
    for (int j = 0; j < L_DIM; j++) {
        float v = item_emb[(size_t)sidx[j] * D_DIM + d];
        S += v;
        if (j >= L_DIM - P_DIM) Slast += v;
    }
    float high = S * (1.0f / L_DIM);
    float low  = Slast * (1.0f / P_DIM);
    float sm = high * S;   // second_mean
    float tm = sm * S;     // third_mean
    float fm = tm * S;     // fourth_mean
    float uni = low + high + (sm + tm + fm) * high;
    float u = user_emb[(size_t)user_ids[b] * D_DIM + d];
    g_x[b * D_DIM + d] = u + uni;
}

// ---------------------------------------------------------------------------
// Kernel 2: out[1024, 100000] = x @ W2^T + b2   (TF32 mma.sync, K=64 one-shot)
// ---------------------------------------------------------------------------
__global__ void __launch_bounds__(256, 2)
gemm_kernel(const float* __restrict__ W2, const float* __restrict__ b2,
            const int* __restrict__ items, float* __restrict__ out) {
    extern __shared__ uint32_t smem[];
    uint32_t* xs  = smem;                 // [BM][KS]
    uint32_t* ws  = smem + BM * KS;       // [BN][KS]
    float*    b2s = (float*)(ws + BN * KS);  // [BN]
    int*      ivs = (int*)(b2s + BN);        // [BN]

    const int m0 = blockIdx.y * BM;
    const int v0 = blockIdx.x * BN;
    const int tid = threadIdx.x;

    // stage item indices + bias for this column tile
    if (tid < BN) {
        int v = v0 + tid;
        if (v < V_DIM) {
            int idx = items[v];
            ivs[tid] = idx;
            b2s[tid] = b2[idx];
        } else {
            ivs[tid] = -1;
            b2s[tid] = 0.f;
        }
    }
    __syncthreads();

    // load x tile [BM,64] and W2 tile [BN,64] into smem as tf32 bits
    {
        int r  = tid >> 4;          // 0..15
        int c4 = (tid & 15) * 4;    // 0,4,...,60
#pragma unroll
        for (int it = 0; it < BM / 16; it++) {
            int row = r + it * 16;
            float4 f = *(const float4*)&g_x[(size_t)(m0 + row) * D_DIM + c4];
            uint32_t* dst = &xs[row * KS + c4];
            dst[0] = cvt_tf32(f.x); dst[1] = cvt_tf32(f.y);
            dst[2] = cvt_tf32(f.z); dst[3] = cvt_tf32(f.w);
        }
#pragma unroll
        for (int it = 0; it < BN / 16; it++) {
            int row = r + it * 16;
            int idx = ivs[row];
            float4 f = make_float4(0.f, 0.f, 0.f, 0.f);
            if (idx >= 0) f = *(const float4*)&W2[(size_t)idx * D_DIM + c4];
            uint32_t* dst = &ws[row * KS + c4];
            dst[0] = cvt_tf32(f.x); dst[1] = cvt_tf32(f.y);
            dst[2] = cvt_tf32(f.z); dst[3] = cvt_tf32(f.w);
        }
    }
    __syncthreads();

    const int warp = tid >> 5, lane = tid & 31;
    const int g = lane >> 2, tg = lane & 3;
    const int wm = (warp & 1) * 64;   // warp M offset
    const int wn = (warp >> 1) * 32;  // warp N offset

    float acc[4][4][4];
#pragma unroll
    for (int ma = 0; ma < 4; ma++)
#pragma unroll
        for (int na = 0; na < 4; na++)
#pragma unroll
            for (int i = 0; i < 4; i++) acc[ma][na][i] = 0.f;

#pragma unroll
    for (int ks = 0; ks < 8; ks++) {
        const int k = ks * 8;
        uint32_t a[4][4];
#pragma unroll
        for (int ma = 0; ma < 4; ma++) {
            int rb = wm + ma * 16;
            a[ma][0] = xs[(rb + g)     * KS + k + tg];
            a[ma][1] = xs[(rb + 8 + g) * KS + k + tg];
            a[ma][2] = xs[(rb + g)     * KS + k + tg + 4];
            a[ma][3] = xs[(rb + 8 + g) * KS + k + tg + 4];
        }
        uint32_t bb[4][2];
#pragma unroll
        for (int na = 0; na < 4; na++) {
            int cb = wn + na * 8 + g;
            bb[na][0] = ws[cb * KS + k + tg];
            bb[na][1] = ws[cb * KS + k + tg + 4];
        }
#pragma unroll
        for (int ma = 0; ma < 4; ma++)
#pragma unroll
            for (int na = 0; na < 4; na++) {
                asm volatile(
                    "mma.sync.aligned.m16n8k8.row.col.f32.tf32.tf32.f32 "
                    "{%0,%1,%2,%3}, {%4,%5,%6,%7}, {%8,%9}, {%0,%1,%2,%3};"
                    : "+f"(acc[ma][na][0]), "+f"(acc[ma][na][1]),
                      "+f"(acc[ma][na][2]), "+f"(acc[ma][na][3])
                    : "r"(a[ma][0]), "r"(a[ma][1]), "r"(a[ma][2]), "r"(a[ma][3]),
                      "r"(bb[na][0]), "r"(bb[na][1]));
            }
    }

    // epilogue: += b2, store
#pragma unroll
    for (int ma = 0; ma < 4; ma++) {
        int r0 = m0 + wm + ma * 16 + g;
#pragma unroll
        for (int na = 0; na < 4; na++) {
            int c = wn + na * 8 + 2 * tg;
            int v = v0 + c;
            if (v + 1 < V_DIM) {
                float bv0 = b2s[c], bv1 = b2s[c + 1];
                float2 o0 = make_float2(acc[ma][na][0] + bv0, acc[ma][na][1] + bv1);
                float2 o1 = make_float2(acc[ma][na][2] + bv0, acc[ma][na][3] + bv1);
                *(float2*)&out[(size_t)r0 * V_DIM + v] = o0;
                *(float2*)&out[(size_t)(r0 + 8) * V_DIM + v] = o1;
            }
        }
    }
}

// ---------------------------------------------------------------------------
extern "C" void kernel_launch(void* const* d_in, const int* in_sizes, int n_in,
                              void* d_out, int out_size) {
    const int*   item_seq = (const int*)d_in[0];
    const int*   user_ids = (const int*)d_in[1];
    const int*   items    = (const int*)d_in[2];
    const float* item_emb = (const float*)d_in[3];
    const float* user_emb = (const float*)d_in[4];
    const float* W2       = (const float*)d_in[5];
    const float* b2       = (const float*)d_in[6];
    float* out = (float*)d_out;

    prep_kernel<<<B_DIM, D_DIM>>>(item_seq, user_ids, item_emb, user_emb);

    const int smem_bytes = (BM * KS + BN * KS) * 4 + BN * 4 + BN * 4;  // ~70.7 KB
    cudaFuncSetAttribute(gemm_kernel, cudaFuncAttributeMaxDynamicSharedMemorySize,
                         smem_bytes);
    dim3 grid((V_DIM + BN - 1) / BN, B_DIM / BM);
    gemm_kernel<<<grid, 256, smem_bytes>>>(W2, b2, items, out);
}

// round 2
// speedup vs baseline: 1.0064x; 1.0064x over previous
#include <cuda_runtime.h>
#include <cstdint>

#define B_DIM 1024
#define L_DIM 50
#define P_DIM 10
#define D_DIM 64
#define V_DIM 100000

#define BM 128
#define BN 128
#define KS 68                                  // padded smem stride (floats)
#define NITER 8
#define NT_TOTAL ((V_DIM + BN - 1) / BN)       // 782
#define GX ((NT_TOTAL + NITER - 1) / NITER)    // 98

// Scratch for the prep result x[B, D] (device global: no allocs allowed)
__device__ float g_x[B_DIM * D_DIM];

// ---------------------------------------------------------------------------
// Kernel 1: x[b,d] = user_emb[uid[b],d] + low + high + high^2*(S + S^2 + S^3)
// ---------------------------------------------------------------------------
__global__ void prep_kernel(const int* __restrict__ item_seq,
                            const int* __restrict__ user_ids,
                            const float* __restrict__ item_emb,
                            const float* __restrict__ user_emb) {
    __shared__ int sidx[L_DIM];
    int b = blockIdx.x;
    int d = threadIdx.x;
    if (d < L_DIM) sidx[d] = item_seq[b * L_DIM + d];
    __syncthreads();

    float S = 0.f, Slast = 0.f;
#pragma unroll
    for (int j = 0; j < L_DIM; j++) {
        float v = item_emb[(size_t)sidx[j] * D_DIM + d];
        S += v;
        if (j >= L_DIM - P_DIM) Slast += v;
    }
    float high = S * (1.0f / L_DIM);
    float low  = Slast * (1.0f / P_DIM);
    float sm = high * S;
    float tm = sm * S;
    float fm = tm * S;
    float uni = low + high + (sm + tm + fm) * high;
    float u = user_emb[(size_t)user_ids[b] * D_DIM + d];
    g_x[b * D_DIM + d] = u + uni;
}

// ---------------------------------------------------------------------------
__device__ __forceinline__ void cp16(uint32_t dst, const float* src) {
    asm volatile("cp.async.cg.shared.global [%0], [%1], 16;\n" :: "r"(dst), "l"(src));
}
__device__ __forceinline__ void cp_commit() {
    asm volatile("cp.async.commit_group;\n" ::);
}
__device__ __forceinline__ void cp_wait1() {
    asm volatile("cp.async.wait_group 1;\n" ::);
}

// ---------------------------------------------------------------------------
// Kernel 2: out[1024, 100000] = x @ W2^T + b2
// Streaming TF32 MMA: x-tile resident, W2 tiles double-buffered via cp.async.
// ---------------------------------------------------------------------------
__global__ void __launch_bounds__(256, 2)
gemm_kernel(const float* __restrict__ W2, const float* __restrict__ b2,
            const int* __restrict__ items, float* __restrict__ out) {
    extern __shared__ float smem[];
    float* xs   = smem;                       // [BM][KS]
    float* wsb0 = smem + BM * KS;             // [BN][KS] buffer 0
    float* wsb1 = wsb0 + BN * KS;             // [BN][KS] buffer 1
    float* bsb0 = wsb1 + BN * KS;             // [BN] bias buffer 0
    float* bsb1 = bsb0 + BN;                  // [BN] bias buffer 1

    const int tid = threadIdx.x;
    const int m0 = blockIdx.y * BM;
    const int tile0 = blockIdx.x * NITER;

    float* wbufs[2] = {wsb0, wsb1};
    float* bbufs[2] = {bsb0, bsb1};

    // --- load resident x tile [BM, 64] (raw fp32; tf32 mma truncates) ---
    {
        int r  = tid >> 4;
        int c4 = (tid & 15) * 4;
#pragma unroll
        for (int it = 0; it < BM / 16; it++) {
            int row = r + it * 16;
            float4 f = *(const float4*)&g_x[(size_t)(m0 + row) * D_DIM + c4];
            *(float4*)&xs[row * KS + c4] = f;
        }
    }

    // cp.async mapping: 2 threads per W2 row, 8x16B chunks each
    const int prow  = tid >> 1;          // 0..127
    const int pcol  = (tid & 1) * 32;    // float offset 0 or 32

    // --- prologue: prefetch tile0 into buffer 0 ---
    {
        int v  = tile0 * BN + prow;
        int vc = v < V_DIM ? v : V_DIM - 1;
        int idx = items[vc];
        const float* src = W2 + (size_t)idx * D_DIM + pcol;
        uint32_t dst = (uint32_t)__cvta_generic_to_shared(&wsb0[prow * KS + pcol]);
#pragma unroll
        for (int j = 0; j < 8; j++) cp16(dst + j * 16, src + j * 4);
        if (tid < BN) {
            int vv  = tile0 * BN + tid;
            int vvc = vv < V_DIM ? vv : V_DIM - 1;
            bsb0[tid] = b2[items[vvc]];
        }
        cp_commit();
    }

    const int warp = tid >> 5, lane = tid & 31;
    const int g  = lane >> 2, tg = lane & 3;
    const int wm = (warp & 1) * 64;
    const int wn = (warp >> 1) * 32;

    for (int t = 0; t < NITER; t++) {
        const int ntile = tile0 + t;
        int ptile = tile0 + t + 1;
        if (ptile >= NT_TOTAL) ptile = NT_TOTAL - 1;

        // --- prefetch next tile into buffer (t+1)&1 ---
        {
            float* wb = wbufs[(t + 1) & 1];
            float* bb = bbufs[(t + 1) & 1];
            int v  = ptile * BN + prow;
            int vc = v < V_DIM ? v : V_DIM - 1;
            int idx = items[vc];
            const float* src = W2 + (size_t)idx * D_DIM + pcol;
            uint32_t dst = (uint32_t)__cvta_generic_to_shared(&wb[prow * KS + pcol]);
#pragma unroll
            for (int j = 0; j < 8; j++) cp16(dst + j * 16, src + j * 4);
            if (tid < BN) {
                int vv  = ptile * BN + tid;
                int vvc = vv < V_DIM ? vv : V_DIM - 1;
                bb[tid] = b2[items[vvc]];
            }
            cp_commit();
        }

        cp_wait1();          // tile t complete (tile t+1 may remain in flight)
        __syncthreads();

        if (ntile < NT_TOTAL) {
            const uint32_t* xsu = (const uint32_t*)xs;
            const uint32_t* wsu = (const uint32_t*)wbufs[t & 1];
            const float*    bs  = bbufs[t & 1];
            const int v0 = ntile * BN;

            float acc[4][4][4];
#pragma unroll
            for (int ma = 0; ma < 4; ma++)
#pragma unroll
                for (int na = 0; na < 4; na++)
#pragma unroll
                    for (int i = 0; i < 4; i++) acc[ma][na][i] = 0.f;

#pragma unroll
            for (int ks8 = 0; ks8 < 8; ks8++) {
                const int k = ks8 * 8;
                uint32_t a[4][4];
#pragma unroll
                for (int ma = 0; ma < 4; ma++) {
                    int rb = wm + ma * 16;
                    a[ma][0] = xsu[(rb + g)     * KS + k + tg];
                    a[ma][1] = xsu[(rb + 8 + g) * KS + k + tg];
                    a[ma][2] = xsu[(rb + g)     * KS + k + tg + 4];
                    a[ma][3] = xsu[(rb + 8 + g) * KS + k + tg + 4];
                }
                uint32_t bbf[4][2];
#pragma unroll
                for (int na = 0; na < 4; na++) {
                    int cb = wn + na * 8 + g;
                    bbf[na][0] = wsu[cb * KS + k + tg];
                    bbf[na][1] = wsu[cb * KS + k + tg + 4];
                }
#pragma unroll
                for (int ma = 0; ma < 4; ma++)
#pragma unroll
                    for (int na = 0; na < 4; na++) {
                        asm volatile(
                            "mma.sync.aligned.m16n8k8.row.col.f32.tf32.tf32.f32 "
                            "{%0,%1,%2,%3}, {%4,%5,%6,%7}, {%8,%9}, {%0,%1,%2,%3};"
                            : "+f"(acc[ma][na][0]), "+f"(acc[ma][na][1]),
                              "+f"(acc[ma][na][2]), "+f"(acc[ma][na][3])
                            : "r"(a[ma][0]), "r"(a[ma][1]), "r"(a[ma][2]), "r"(a[ma][3]),
                              "r"(bbf[na][0]), "r"(bbf[na][1]));
                    }
            }

            // --- epilogue: += b2, store float2 ---
#pragma unroll
            for (int ma = 0; ma < 4; ma++) {
                int r0 = m0 + wm + ma * 16 + g;
#pragma unroll
                for (int na = 0; na < 4; na++) {
                    int c = wn + na * 8 + 2 * tg;
                    int v = v0 + c;
                    if (v < V_DIM) {
                        float bv0 = bs[c], bv1 = bs[c + 1];
                        float2 o0 = make_float2(acc[ma][na][0] + bv0, acc[ma][na][1] + bv1);
                        float2 o1 = make_float2(acc[ma][na][2] + bv0, acc[ma][na][3] + bv1);
                        *(float2*)&out[(size_t)r0 * V_DIM + v] = o0;
                        *(float2*)&out[(size_t)(r0 + 8) * V_DIM + v] = o1;
                    }
                }
            }
        }
        __syncthreads();   // protect buffer (t+1)&1... and buffer t&1 before reuse
    }
}

// ---------------------------------------------------------------------------
extern "C" void kernel_launch(void* const* d_in, const int* in_sizes, int n_in,
                              void* d_out, int out_size) {
    const int*   item_seq = (const int*)d_in[0];
    const int*   user_ids = (const int*)d_in[1];
    const int*   items    = (const int*)d_in[2];
    const float* item_emb = (const float*)d_in[3];
    const float* user_emb = (const float*)d_in[4];
    const float* W2       = (const float*)d_in[5];
    const float* b2       = (const float*)d_in[6];
    float* out = (float*)d_out;

    prep_kernel<<<B_DIM, D_DIM>>>(item_seq, user_ids, item_emb, user_emb);

    const int smem_bytes = (BM * KS + 2 * BN * KS + 2 * BN) * 4;  // ~103 KB
    cudaFuncSetAttribute(gemm_kernel, cudaFuncAttributeMaxDynamicSharedMemorySize,
                         smem_bytes);
    dim3 grid(GX, B_DIM / BM);
    gemm_kernel<<<grid, 256, smem_bytes>>>(W2, b2, items, out);
}